// round 1
// baseline (speedup 1.0000x reference)
#include <cuda_runtime.h>
#include <math.h>

// Problem constants (fixed by the reference):
//   B=64, T=512, D_IN=K=512, H=N=512.  M = B*T = 32768.
#define BB   64
#define TT   512
#define KK   512
#define HH   512
#define MM   (BB * TT)          // 32768

// GEMM tiling
#define BM   128
#define BN   128
#define BKT  16
#define NKT  (KK / BKT)         // 32 k-tiles

// Scratch: three projections xz, xr, xh, each [M, H] fp32 (64 MB each).
__device__ float g_proj[3][(size_t)MM * HH];

// ---------------------------------------------------------------------------
// GEMM: computes g_proj[w] = x @ W_w for w in {0:kz, 1:kr, 2:kh}.
// blockIdx.x in [0,12): w = x>>2 selects weight, (x&3)*128 selects n-tile.
// blockIdx.y in [0,256): m-tile.
// 256 threads, each computes an 8x8 microtile of a 128x128 block tile.
// Double-buffered SMEM, one __syncthreads per k-tile.
// ---------------------------------------------------------------------------
__global__ __launch_bounds__(256, 2)
void brc_gemm3_kernel(const float* __restrict__ x,
                      const float* __restrict__ kz,
                      const float* __restrict__ kr,
                      const float* __restrict__ kh)
{
    const int ntile = blockIdx.x;            // 0..11
    const int mtile = blockIdx.y;            // 0..255
    const int w     = ntile >> 2;            // which weight / output
    const int n0    = (ntile & 3) * BN;
    const int m0    = mtile * BM;

    const float* __restrict__ W = (w == 0) ? kz : (w == 1) ? kr : kh;
    float* __restrict__ C = g_proj[w];

    __shared__ float As[2][BKT][BM + 4];     // A stored k-major (transposed)
    __shared__ float Bs[2][BKT][BN];

    const int tid = threadIdx.x;

    // Per-thread load assignments (2 float4 each for A and B per k-tile):
    //   A tile: 128 rows x 16 k -> 512 float4; j = tid + s*256
    //           row = j>>2, kq = j&3  (float4 within the 16-wide k row)
    //   B tile: 16 k-rows x 128 n -> 512 float4; krow = j>>5, nq = j&31
    float4 aReg[2], bReg[2];

    const int aRow0 = (tid + 0)   >> 2, aKq0 = (tid + 0)   & 3;
    const int aRow1 = (tid + 256) >> 2, aKq1 = (tid + 256) & 3;
    const int bKr0  = (tid + 0)   >> 5, bNq0 = (tid + 0)   & 31;
    const int bKr1  = (tid + 256) >> 5, bNq1 = (tid + 256) & 31;

    // ---- prologue: load k-tile 0 ----
    {
        const int kb = 0;
        aReg[0] = *(const float4*)&x[(size_t)(m0 + aRow0) * KK + kb + aKq0 * 4];
        aReg[1] = *(const float4*)&x[(size_t)(m0 + aRow1) * KK + kb + aKq1 * 4];
        bReg[0] = *(const float4*)&W[(size_t)(kb + bKr0) * HH + n0 + bNq0 * 4];
        bReg[1] = *(const float4*)&W[(size_t)(kb + bKr1) * HH + n0 + bNq1 * 4];

        As[0][aKq0 * 4 + 0][aRow0] = aReg[0].x;
        As[0][aKq0 * 4 + 1][aRow0] = aReg[0].y;
        As[0][aKq0 * 4 + 2][aRow0] = aReg[0].z;
        As[0][aKq0 * 4 + 3][aRow0] = aReg[0].w;
        As[0][aKq1 * 4 + 0][aRow1] = aReg[1].x;
        As[0][aKq1 * 4 + 1][aRow1] = aReg[1].y;
        As[0][aKq1 * 4 + 2][aRow1] = aReg[1].z;
        As[0][aKq1 * 4 + 3][aRow1] = aReg[1].w;
        *(float4*)&Bs[0][bKr0][bNq0 * 4] = bReg[0];
        *(float4*)&Bs[0][bKr1][bNq1 * 4] = bReg[1];
    }
    __syncthreads();

    float acc[8][8];
    #pragma unroll
    for (int i = 0; i < 8; i++)
        #pragma unroll
        for (int j = 0; j < 8; j++) acc[i][j] = 0.0f;

    const int tm = (tid >> 4) * 8;
    const int tn = (tid & 15) * 8;

    for (int kt = 0; kt < NKT; kt++) {
        // Issue global loads for next tile early (latency hidden by compute).
        if (kt + 1 < NKT) {
            const int kb = (kt + 1) * BKT;
            aReg[0] = *(const float4*)&x[(size_t)(m0 + aRow0) * KK + kb + aKq0 * 4];
            aReg[1] = *(const float4*)&x[(size_t)(m0 + aRow1) * KK + kb + aKq1 * 4];
            bReg[0] = *(const float4*)&W[(size_t)(kb + bKr0) * HH + n0 + bNq0 * 4];
            bReg[1] = *(const float4*)&W[(size_t)(kb + bKr1) * HH + n0 + bNq1 * 4];
        }

        const int buf = kt & 1;
        #pragma unroll
        for (int k = 0; k < BKT; k++) {
            float a[8], b[8];
            float4 t0 = *(const float4*)&As[buf][k][tm];
            float4 t1 = *(const float4*)&As[buf][k][tm + 4];
            float4 t2 = *(const float4*)&Bs[buf][k][tn];
            float4 t3 = *(const float4*)&Bs[buf][k][tn + 4];
            a[0]=t0.x; a[1]=t0.y; a[2]=t0.z; a[3]=t0.w;
            a[4]=t1.x; a[5]=t1.y; a[6]=t1.z; a[7]=t1.w;
            b[0]=t2.x; b[1]=t2.y; b[2]=t2.z; b[3]=t2.w;
            b[4]=t3.x; b[5]=t3.y; b[6]=t3.z; b[7]=t3.w;
            #pragma unroll
            for (int i = 0; i < 8; i++)
                #pragma unroll
                for (int j = 0; j < 8; j++)
                    acc[i][j] = fmaf(a[i], b[j], acc[i][j]);
        }

        // Store next tile into the other buffer. Safe: every thread finished
        // reading that buffer before the sync that ended iteration kt-1.
        if (kt + 1 < NKT) {
            const int nb = (kt + 1) & 1;
            As[nb][aKq0 * 4 + 0][aRow0] = aReg[0].x;
            As[nb][aKq0 * 4 + 1][aRow0] = aReg[0].y;
            As[nb][aKq0 * 4 + 2][aRow0] = aReg[0].z;
            As[nb][aKq0 * 4 + 3][aRow0] = aReg[0].w;
            As[nb][aKq1 * 4 + 0][aRow1] = aReg[1].x;
            As[nb][aKq1 * 4 + 1][aRow1] = aReg[1].y;
            As[nb][aKq1 * 4 + 2][aRow1] = aReg[1].z;
            As[nb][aKq1 * 4 + 3][aRow1] = aReg[1].w;
            *(float4*)&Bs[nb][bKr0][bNq0 * 4] = bReg[0];
            *(float4*)&Bs[nb][bKr1][bNq1 * 4] = bReg[1];
        }
        __syncthreads();
    }

    // Epilogue: write 8x8 microtile as float4s.
    #pragma unroll
    for (int i = 0; i < 8; i++) {
        size_t rowoff = (size_t)(m0 + tm + i) * HH + n0 + tn;
        float4 o0 = make_float4(acc[i][0], acc[i][1], acc[i][2], acc[i][3]);
        float4 o1 = make_float4(acc[i][4], acc[i][5], acc[i][6], acc[i][7]);
        *(float4*)&C[rowoff]     = o0;
        *(float4*)&C[rowoff + 4] = o1;
    }
}

// ---------------------------------------------------------------------------
// Scan: one thread per (b, h) channel; serial over t. Fully coalesced across
// h (adjacent threads -> adjacent addresses). #pragma unroll 4 lets the
// compiler batch the (h-independent) loads of future timesteps for MLP.
// ---------------------------------------------------------------------------
__global__ __launch_bounds__(128)
void brc_scan_kernel(const float* __restrict__ h0,
                     const float* __restrict__ mz,
                     const float* __restrict__ mr,
                     const float* __restrict__ bz,
                     const float* __restrict__ br,
                     float* __restrict__ out)
{
    const int idx = blockIdx.x * blockDim.x + threadIdx.x;   // 0 .. B*H-1
    const int b = idx >> 9;          // / 512
    const int h = idx & 511;         // % 512

    float hc  = h0[idx];
    const float vmz = mz[h];
    const float vmr = mr[h];
    const float vbz = bz[h];
    const float vbr = br[h];

    const float* __restrict__ xz = g_proj[0];
    const float* __restrict__ xr = g_proj[1];
    const float* __restrict__ xh = g_proj[2];

    size_t base = (size_t)b * TT * HH + h;

    #pragma unroll 4
    for (int t = 0; t < TT; t++) {
        size_t off = base + (size_t)t * HH;
        float az = xz[off] + vbz;
        float ar = xr[off] + vbr;
        float ah = xh[off];

        float r    = tanhf(fmaf(hc, vmr, ar)) + 1.0f;
        float zg   = 1.0f / (1.0f + expf(-fmaf(hc, vmz, az)));
        float cand = tanhf(fmaf(r, hc, ah));
        hc = zg * hc + (1.0f - zg) * cand;

        out[off] = hc;
    }
}

// ---------------------------------------------------------------------------
// Launch. Inputs (metadata order): x, h0, kz, kr, kh, mz, mr, bz, br.
// Output: [B, T, H] fp32.
// ---------------------------------------------------------------------------
extern "C" void kernel_launch(void* const* d_in, const int* in_sizes, int n_in,
                              void* d_out, int out_size)
{
    const float* x  = (const float*)d_in[0];
    const float* h0 = (const float*)d_in[1];
    const float* kz = (const float*)d_in[2];
    const float* kr = (const float*)d_in[3];
    const float* kh = (const float*)d_in[4];
    const float* mz = (const float*)d_in[5];
    const float* mr = (const float*)d_in[6];
    const float* bz = (const float*)d_in[7];
    const float* br = (const float*)d_in[8];
    float* out = (float*)d_out;

    dim3 ggrid(12, MM / BM);                 // 12 n-tiles x 256 m-tiles
    brc_gemm3_kernel<<<ggrid, 256>>>(x, kz, kr, kh);

    brc_scan_kernel<<<(BB * HH) / 128, 128>>>(h0, mz, mr, bz, br, out);
}

// round 4
// speedup vs baseline: 2.7966x; 2.7966x over previous
#include <cuda_runtime.h>
#include <cuda_bf16.h>
#include <cstdint>
#include <math.h>

// Problem constants: B=64, T=512, K=512, H=512. M = B*T = 32768.
#define BB   64
#define TT   512
#define KK   512
#define HH   512
#define MM   (BB * TT)          // 32768
#define KP   (3 * KK)           // 1536 = interleaved split-K  [hi | hi | lo]

// ---------------------------------------------------------------------------
// Scratch (__device__ globals; no allocations allowed)
// ---------------------------------------------------------------------------
__device__ float         g_proj[3][(size_t)MM * HH];        // xz, xr, xh
__device__ __nv_bfloat16 g_xs[(size_t)MM * KP];             // A' [m][k']
__device__ __nv_bfloat16 g_ws[3ull * HH * KP];              // B' [w][n][k'] (transposed)

// ---------------------------------------------------------------------------
// Helpers (sm_80-compatible PTX only: ldmatrix / mma.sync / cp.async)
// ---------------------------------------------------------------------------
__device__ __forceinline__ uint32_t smem_u32(const void* p) {
    uint32_t a;
    asm("{ .reg .u64 t; cvta.to.shared.u64 t, %1; cvt.u32.u64 %0, t; }" : "=r"(a) : "l"(p));
    return a;
}

__device__ __forceinline__ void cpa16(uint32_t saddr, const void* g) {
    asm volatile("cp.async.cg.shared.global [%0], [%1], 16;" :: "r"(saddr), "l"(g));
}
__device__ __forceinline__ void cpa4(uint32_t saddr, const void* g) {
    asm volatile("cp.async.ca.shared.global [%0], [%1], 4;" :: "r"(saddr), "l"(g));
}
#define CP_COMMIT() asm volatile("cp.async.commit_group;" ::: "memory")
template <int N>
__device__ __forceinline__ void cp_wait() {
    asm volatile("cp.async.wait_group %0;" :: "n"(N) : "memory");
}

__device__ __forceinline__ void ldsm_x4(uint32_t* r, uint32_t addr) {
    asm volatile("ldmatrix.sync.aligned.m8n8.x4.shared.b16 {%0,%1,%2,%3}, [%4];"
                 : "=r"(r[0]), "=r"(r[1]), "=r"(r[2]), "=r"(r[3]) : "r"(addr));
}
__device__ __forceinline__ void ldsm_x2(uint32_t* r, uint32_t addr) {
    asm volatile("ldmatrix.sync.aligned.m8n8.x2.shared.b16 {%0,%1}, [%2];"
                 : "=r"(r[0]), "=r"(r[1]) : "r"(addr));
}
__device__ __forceinline__ void mma_bf16(float* d, const uint32_t* a, const uint32_t* b) {
    asm volatile(
        "mma.sync.aligned.m16n8k16.row.col.f32.bf16.bf16.f32 "
        "{%0,%1,%2,%3}, {%4,%5,%6,%7}, {%8,%9}, {%0,%1,%2,%3};"
        : "+f"(d[0]), "+f"(d[1]), "+f"(d[2]), "+f"(d[3])
        : "r"(a[0]), "r"(a[1]), "r"(a[2]), "r"(a[3]), "r"(b[0]), "r"(b[1]));
}

// ---------------------------------------------------------------------------
// Convert x: fp32 -> A' = [hi | hi | lo] along K'. One float4 per thread.
// ---------------------------------------------------------------------------
__global__ void cvt_x_kernel(const float* __restrict__ x) {
    size_t i4 = (size_t)blockIdx.x * blockDim.x + threadIdx.x;      // float4 index
    size_t m  = i4 >> 7;                 // / (512/4)
    size_t k4 = i4 & 127;                // float4 within row
    float4 v = ((const float4*)x)[i4];
    float a[4] = {v.x, v.y, v.z, v.w};
    __nv_bfloat16 h[4], l[4];
    #pragma unroll
    for (int j = 0; j < 4; j++) {
        h[j] = __float2bfloat16_rn(a[j]);
        l[j] = __float2bfloat16_rn(a[j] - __bfloat162float(h[j]));
    }
    __nv_bfloat16* rp = g_xs + m * KP + k4 * 4;
    *(uint2*)(rp)            = *(uint2*)h;      // block 0: hi
    *(uint2*)(rp + KK)       = *(uint2*)h;      // block 1: hi
    *(uint2*)(rp + 2 * KK)   = *(uint2*)l;      // block 2: lo
}

// ---------------------------------------------------------------------------
// Convert weights: W[k][n] fp32 -> B'[w][n][k'] = [hi | lo | hi] (transposed).
// k fastest across threads -> coalesced writes; reads hit L2 (sectors shared
// by 8 adjacent-n warps). Only 3 MB of input.
// ---------------------------------------------------------------------------
__global__ void cvt_w_kernel(const float* __restrict__ kz,
                             const float* __restrict__ kr,
                             const float* __restrict__ kh) {
    int j = blockIdx.x * blockDim.x + threadIdx.x;   // 0 .. 3*512*512-1
    int w = j >> 18;
    int n = (j >> 9) & 511;
    int k = j & 511;
    const float* W = (w == 0) ? kz : (w == 1) ? kr : kh;
    float a = W[k * HH + n];
    __nv_bfloat16 h = __float2bfloat16_rn(a);
    __nv_bfloat16 l = __float2bfloat16_rn(a - __bfloat162float(h));
    __nv_bfloat16* rp = g_ws + ((size_t)w * HH + n) * KP + k;
    rp[0]       = h;     // block 0: hi   (pairs with A hi -> hi*hi)
    rp[KK]      = l;     // block 1: lo   (pairs with A hi -> hi*lo)
    rp[2 * KK]  = h;     // block 2: hi   (pairs with A lo -> lo*hi)
}

// ---------------------------------------------------------------------------
// GEMM: g_proj[w] = A'(32768 x 1536) @ B'_w^T, bf16 mma.sync, fp32 accum.
// Block 128x128x32, 256 threads = 8 warps (2m x 4n -> 64x32 warp tiles).
// 4-stage cp.async pipeline. Smem rows are 64B (=4 16B chunks), XOR-swizzled
// chunk ^= (row>>1)&3 so ldmatrix's 8 row-reads hit 8 distinct 16B groups.
// ---------------------------------------------------------------------------
#define GBM 128
#define GBN 128
#define GBK 32
#define NKT (KP / GBK)          // 48
#define GSTAGES 4
#define A_STG (GBM * GBK * 2)   // 8192 B
#define B_STG (GBN * GBK * 2)   // 8192 B
#define STG_BYTES (A_STG + B_STG)
#define GSMEM (GSTAGES * STG_BYTES)   // 65536 B

__global__ __launch_bounds__(256, 2)
void brc_mma_gemm(void) {
    extern __shared__ char smem[];
    const uint32_t sbase = smem_u32(smem);
    const int tid  = threadIdx.x;
    const int lane = tid & 31;
    const int wid  = tid >> 5;
    const int wm   = wid >> 2;          // 0..1  (m group)
    const int wn   = wid & 3;           // 0..3  (n group)

    const int w  = blockIdx.x >> 2;
    const int n0 = (blockIdx.x & 3) * GBN;
    const int m0 = blockIdx.y * GBM;

    const __nv_bfloat16* __restrict__ Ap = g_xs;
    const __nv_bfloat16* __restrict__ Bp = g_ws + (size_t)w * HH * KP;
    float* __restrict__ C = g_proj[w];

    // per-thread load slots: chunks tid and tid+256 of 512 (row = c>>2, chunk = c&3)
    const int lrow0 = tid >> 2,          lc0 = tid & 3;
    const int lrow1 = (tid + 256) >> 2,  lc1 = (tid + 256) & 3;
    const uint32_t so0 = lrow0 * 64 + ((lc0 ^ ((lrow0 >> 1) & 3)) * 16);
    const uint32_t so1 = lrow1 * 64 + ((lc1 ^ ((lrow1 >> 1) & 3)) * 16);

    auto load_stage = [&](int kt, int s) {
        const uint32_t sa = sbase + s * STG_BYTES;
        const uint32_t sb = sa + A_STG;
        const size_t kb = (size_t)kt * GBK;
        cpa16(sa + so0, Ap + (size_t)(m0 + lrow0) * KP + kb + lc0 * 8);
        cpa16(sa + so1, Ap + (size_t)(m0 + lrow1) * KP + kb + lc1 * 8);
        cpa16(sb + so0, Bp + (size_t)(n0 + lrow0) * KP + kb + lc0 * 8);
        cpa16(sb + so1, Bp + (size_t)(n0 + lrow1) * KP + kb + lc1 * 8);
    };

    // prologue: stages 0..GSTAGES-2
    #pragma unroll
    for (int s = 0; s < GSTAGES - 1; s++) { load_stage(s, s); CP_COMMIT(); }

    float acc[4][4][4];
    #pragma unroll
    for (int i = 0; i < 4; i++)
        #pragma unroll
        for (int j = 0; j < 4; j++)
            #pragma unroll
            for (int q = 0; q < 4; q++) acc[i][j][q] = 0.0f;

    // ldmatrix lane geometry (invariant)
    const int a_r = lane & 15;              // row within 16-row frag
    const int a_c = lane >> 4;              // 8-col block (0/1)
    const int b_r = lane & 7;               // row within 8-row frag
    const int b_c = (lane >> 3) & 1;        // 8-col block (0/1)

    for (int kt = 0; kt < NKT; kt++) {
        cp_wait<GSTAGES - 2>();
        __syncthreads();

        // prefetch into the stage consumed last iteration
        if (kt + GSTAGES - 1 < NKT)
            load_stage(kt + GSTAGES - 1, (kt + GSTAGES - 1) & (GSTAGES - 1));
        CP_COMMIT();

        const uint32_t sa = sbase + (kt & (GSTAGES - 1)) * STG_BYTES;
        const uint32_t sb = sa + A_STG;

        #pragma unroll
        for (int ks = 0; ks < 2; ks++) {
            uint32_t afr[4][4], bfr[4][2];
            #pragma unroll
            for (int mi = 0; mi < 4; mi++) {
                int row = wm * 64 + mi * 16 + a_r;
                int c   = ks * 2 + a_c;
                ldsm_x4(afr[mi], sa + row * 64 + ((c ^ ((row >> 1) & 3)) * 16));
            }
            #pragma unroll
            for (int ni = 0; ni < 4; ni++) {
                int row = wn * 32 + ni * 8 + b_r;
                int c   = ks * 2 + b_c;
                ldsm_x2(bfr[ni], sb + row * 64 + ((c ^ ((row >> 1) & 3)) * 16));
            }
            #pragma unroll
            for (int mi = 0; mi < 4; mi++)
                #pragma unroll
                for (int ni = 0; ni < 4; ni++)
                    mma_bf16(acc[mi][ni], afr[mi], bfr[ni]);
        }
        __syncthreads();
    }

    // epilogue: thread t holds rows (t/4, t/4+8), cols 2*(t%4)+{0,1} per frag
    const int er = lane >> 2;
    const int ec = (lane & 3) * 2;
    #pragma unroll
    for (int mi = 0; mi < 4; mi++) {
        #pragma unroll
        for (int ni = 0; ni < 4; ni++) {
            int gr = m0 + wm * 64 + mi * 16 + er;
            int gc = n0 + wn * 32 + ni * 8 + ec;
            float2 v0 = make_float2(acc[mi][ni][0], acc[mi][ni][1]);
            float2 v1 = make_float2(acc[mi][ni][2], acc[mi][ni][3]);
            *(float2*)&C[(size_t)gr * HH + gc]       = v0;
            *(float2*)&C[(size_t)(gr + 8) * HH + gc] = v1;
        }
    }
}

// ---------------------------------------------------------------------------
// Scan: 1 thread per (b, h). cp.async ring (depth 15) hides DRAM latency;
// accurate tanhf/expf (R1-proven numerics, rel_err 1.4e-7).
// ---------------------------------------------------------------------------
#define STAGES 16

__global__ __launch_bounds__(128)
void brc_scan_kernel(const float* __restrict__ h0,
                     const float* __restrict__ mz,
                     const float* __restrict__ mr,
                     const float* __restrict__ bz,
                     const float* __restrict__ br,
                     float* __restrict__ out)
{
    __shared__ float ring[STAGES][3][128];

    const int tid = threadIdx.x;
    const int idx = blockIdx.x * 128 + tid;
    const int b = idx >> 9;
    const int h = idx & 511;

    float hc        = h0[idx];
    const float vmz = mz[h];
    const float vmr = mr[h];
    const float vbz = bz[h];
    const float vbr = br[h];

    const float* __restrict__ xz = g_proj[0];
    const float* __restrict__ xr = g_proj[1];
    const float* __restrict__ xh = g_proj[2];

    const size_t base = (size_t)b * TT * HH + h;

    const uint32_t s0 = smem_u32(&ring[0][0][tid]);
    const uint32_t stage_stride = 3 * 128 * 4;
    const uint32_t arr_stride   = 128 * 4;

    #pragma unroll
    for (int s = 0; s < STAGES - 1; s++) {          // prologue: stages 0..14
        size_t off = base + (size_t)s * HH;
        uint32_t sa = s0 + s * stage_stride;
        cpa4(sa,                  xz + off);
        cpa4(sa + arr_stride,     xr + off);
        cpa4(sa + 2 * arr_stride, xh + off);
        CP_COMMIT();
    }

    for (int t = 0; t < TT; t++) {
        cp_wait<STAGES - 2>();                      // stage t landed
        const int s = t & (STAGES - 1);
        float az = ring[s][0][tid] + vbz;
        float ar = ring[s][1][tid] + vbr;
        float ah = ring[s][2][tid];

        float r    = tanhf(fmaf(hc, vmr, ar)) + 1.0f;
        float zg   = 1.0f / (1.0f + expf(-fmaf(hc, vmz, az)));
        float cand = tanhf(fmaf(r, hc, ah));
        hc = fmaf(zg, hc - cand, cand);

        out[base + (size_t)t * HH] = hc;

        const int tn = t + STAGES - 1;              // refill consumed stage
        if (tn < TT) {
            size_t off = base + (size_t)tn * HH;
            uint32_t sa = s0 + (tn & (STAGES - 1)) * stage_stride;
            cpa4(sa,                  xz + off);
            cpa4(sa + arr_stride,     xr + off);
            cpa4(sa + 2 * arr_stride, xh + off);
        }
        CP_COMMIT();                                // keep group count stable
    }
}

// ---------------------------------------------------------------------------
// Launch. Inputs: x, h0, kz, kr, kh, mz, mr, bz, br. Output: [B, T, H] fp32.
// ---------------------------------------------------------------------------
extern "C" void kernel_launch(void* const* d_in, const int* in_sizes, int n_in,
                              void* d_out, int out_size)
{
    const float* x  = (const float*)d_in[0];
    const float* h0 = (const float*)d_in[1];
    const float* kz = (const float*)d_in[2];
    const float* kr = (const float*)d_in[3];
    const float* kh = (const float*)d_in[4];
    const float* mz = (const float*)d_in[5];
    const float* mr = (const float*)d_in[6];
    const float* bz = (const float*)d_in[7];
    const float* br = (const float*)d_in[8];
    float* out = (float*)d_out;

    cudaFuncSetAttribute(brc_mma_gemm, cudaFuncAttributeMaxDynamicSharedMemorySize,
                         GSMEM);

    cvt_x_kernel<<<(MM * KK / 4) / 256, 256>>>(x);
    cvt_w_kernel<<<(3 * HH * KK) / 256, 256>>>(kz, kr, kh);

    dim3 ggrid(12, MM / GBM);          // (w, n-tile) fast -> A m-block L2 reuse x12
    brc_mma_gemm<<<ggrid, 256, GSMEM>>>();

    brc_scan_kernel<<<(BB * HH) / 128, 128>>>(h0, mz, mr, bz, br, out);
}

// round 5
// speedup vs baseline: 3.9202x; 1.4018x over previous
#include <cuda_runtime.h>
#include <cuda_fp16.h>
#include <cstdint>
#include <math.h>

// Problem constants: B=64, T=512, K=512, H=512. M = B*T = 32768.
#define BB   64
#define TT   512
#define KK   512
#define HH   512
#define MM   (BB * TT)          // 32768
#define KP2  1024               // split-K: A' = [hi | lo], B' = [hi | hi]

// ---------------------------------------------------------------------------
// Scratch (__device__ globals; no allocations allowed)
// ---------------------------------------------------------------------------
__device__ float  g_proj[3][(size_t)MM * HH];        // xz, xr, xh
__device__ __half g_xs[(size_t)MM * KP2];            // A' [m][k']
__device__ __half g_ws[3ull * HH * KP2];             // B' [w][n][k'] (transposed)

// ---------------------------------------------------------------------------
// Helpers (sm_80-compatible PTX: ldmatrix / mma.sync / cp.async)
// ---------------------------------------------------------------------------
__device__ __forceinline__ uint32_t smem_u32(const void* p) {
    uint32_t a;
    asm("{ .reg .u64 t; cvta.to.shared.u64 t, %1; cvt.u32.u64 %0, t; }" : "=r"(a) : "l"(p));
    return a;
}

__device__ __forceinline__ void cpa16(uint32_t saddr, const void* g) {
    asm volatile("cp.async.cg.shared.global [%0], [%1], 16;" :: "r"(saddr), "l"(g));
}
__device__ __forceinline__ void cpa4(uint32_t saddr, const void* g) {
    asm volatile("cp.async.ca.shared.global [%0], [%1], 4;" :: "r"(saddr), "l"(g));
}
#define CP_COMMIT() asm volatile("cp.async.commit_group;" ::: "memory")
template <int N>
__device__ __forceinline__ void cp_wait() {
    asm volatile("cp.async.wait_group %0;" :: "n"(N) : "memory");
}

__device__ __forceinline__ void ldsm_x4(uint32_t* r, uint32_t addr) {
    asm volatile("ldmatrix.sync.aligned.m8n8.x4.shared.b16 {%0,%1,%2,%3}, [%4];"
                 : "=r"(r[0]), "=r"(r[1]), "=r"(r[2]), "=r"(r[3]) : "r"(addr));
}
__device__ __forceinline__ void mma_f16(float* d, const uint32_t* a, const uint32_t* b) {
    asm volatile(
        "mma.sync.aligned.m16n8k16.row.col.f32.f16.f16.f32 "
        "{%0,%1,%2,%3}, {%4,%5,%6,%7}, {%8,%9}, {%0,%1,%2,%3};"
        : "+f"(d[0]), "+f"(d[1]), "+f"(d[2]), "+f"(d[3])
        : "r"(a[0]), "r"(a[1]), "r"(a[2]), "r"(a[3]), "r"(b[0]), "r"(b[1]));
}

// Fast activations: MUFU-based, ~2 ulp, robust at +/-inf (no clamps needed).
__device__ __forceinline__ float sigmoid_fast(float x) {
    return __fdividef(1.0f, 1.0f + __expf(-x));
}
__device__ __forceinline__ float tanh_fast2(float x) {
    return __fdividef(2.0f, 1.0f + __expf(-2.0f * x)) - 1.0f;
}

// ---------------------------------------------------------------------------
// Convert x: fp32 -> A' = [hi | lo] fp16 along K'. One float4 per thread.
// ---------------------------------------------------------------------------
__global__ void cvt_x_kernel(const float* __restrict__ x) {
    size_t i4 = (size_t)blockIdx.x * blockDim.x + threadIdx.x;   // float4 index
    size_t m  = i4 >> 7;
    size_t k4 = i4 & 127;
    float4 v = ((const float4*)x)[i4];
    float a[4] = {v.x, v.y, v.z, v.w};
    __half h[4], l[4];
    #pragma unroll
    for (int j = 0; j < 4; j++) {
        h[j] = __float2half_rn(a[j]);
        l[j] = __float2half_rn(a[j] - __half2float(h[j]));
    }
    __half* rp = g_xs + m * KP2 + k4 * 4;
    *(uint2*)(rp)      = *(uint2*)h;     // block 0: hi
    *(uint2*)(rp + KK) = *(uint2*)l;     // block 1: lo
}

// ---------------------------------------------------------------------------
// Convert weights with coalesced smem transpose: W[k][n] -> B'[w][n][hi|hi].
// Block (32,8): 32x32 tile; reads and writes both coalesced.
// ---------------------------------------------------------------------------
__global__ void cvt_w_kernel(const float* __restrict__ kz,
                             const float* __restrict__ kr,
                             const float* __restrict__ kh) {
    __shared__ float tile[32][33];
    const int w  = blockIdx.z;
    const int k0 = blockIdx.x * 32;
    const int n0 = blockIdx.y * 32;
    const int tx = threadIdx.x, ty = threadIdx.y;
    const float* __restrict__ W = (w == 0) ? kz : (w == 1) ? kr : kh;

    #pragma unroll
    for (int r = 0; r < 4; r++)
        tile[ty + r * 8][tx] = W[(size_t)(k0 + ty + r * 8) * HH + n0 + tx];
    __syncthreads();

    #pragma unroll
    for (int r = 0; r < 4; r++) {
        int n = n0 + ty + r * 8;
        int k = k0 + tx;
        __half h = __float2half_rn(tile[tx][ty + r * 8]);
        __half* rp = g_ws + ((size_t)w * HH + n) * KP2;
        rp[k]      = h;                  // block 0: hi (pairs with A hi)
        rp[KK + k] = h;                  // block 1: hi (pairs with A lo)
    }
}

// ---------------------------------------------------------------------------
// GEMM: g_proj[w] = A'(32768 x 1024) @ B'_w^T, fp16 mma.sync, fp32 accum.
// Block 128x128x32, 8 warps (2m x 4n -> 64x32 warp tiles), 4-stage cp.async.
// Smem rows 64B (4 x 16B chunks), XOR swizzle chunk ^= (row>>1)&3.
// ---------------------------------------------------------------------------
#define GBM 128
#define GBN 128
#define GBK 32
#define NKT (KP2 / GBK)         // 32
#define GSTAGES 4
#define A_STG (GBM * GBK * 2)   // 8192 B
#define B_STG (GBN * GBK * 2)   // 8192 B
#define STG_BYTES (A_STG + B_STG)
#define GSMEM (GSTAGES * STG_BYTES)   // 65536 B

__global__ __launch_bounds__(256, 2)
void brc_mma_gemm(void) {
    extern __shared__ char smem[];
    const uint32_t sbase = smem_u32(smem);
    const int tid  = threadIdx.x;
    const int lane = tid & 31;
    const int wid  = tid >> 5;
    const int wm   = wid >> 2;          // 0..1  (m group)
    const int wn   = wid & 3;           // 0..3  (n group)

    const int w  = blockIdx.x >> 2;
    const int n0 = (blockIdx.x & 3) * GBN;
    const int m0 = blockIdx.y * GBM;

    const __half* __restrict__ Ap = g_xs;
    const __half* __restrict__ Bp = g_ws + (size_t)w * HH * KP2;
    float* __restrict__ C = g_proj[w];

    // per-thread load slots: chunks tid and tid+256 of 512 (row = c>>2, chunk = c&3)
    const int lrow0 = tid >> 2,          lc0 = tid & 3;
    const int lrow1 = (tid + 256) >> 2,  lc1 = (tid + 256) & 3;
    const uint32_t so0 = lrow0 * 64 + ((lc0 ^ ((lrow0 >> 1) & 3)) * 16);
    const uint32_t so1 = lrow1 * 64 + ((lc1 ^ ((lrow1 >> 1) & 3)) * 16);

    auto load_stage = [&](int kt, int s) {
        const uint32_t sa = sbase + s * STG_BYTES;
        const uint32_t sb = sa + A_STG;
        const size_t kb = (size_t)kt * GBK;
        cpa16(sa + so0, Ap + (size_t)(m0 + lrow0) * KP2 + kb + lc0 * 8);
        cpa16(sa + so1, Ap + (size_t)(m0 + lrow1) * KP2 + kb + lc1 * 8);
        cpa16(sb + so0, Bp + (size_t)(n0 + lrow0) * KP2 + kb + lc0 * 8);
        cpa16(sb + so1, Bp + (size_t)(n0 + lrow1) * KP2 + kb + lc1 * 8);
    };

    #pragma unroll
    for (int s = 0; s < GSTAGES - 1; s++) { load_stage(s, s); CP_COMMIT(); }

    float acc[4][4][4];
    #pragma unroll
    for (int i = 0; i < 4; i++)
        #pragma unroll
        for (int j = 0; j < 4; j++)
            #pragma unroll
            for (int q = 0; q < 4; q++) acc[i][j][q] = 0.0f;

    // ldmatrix lane geometry
    const int a_r = lane & 15;              // A: row within 16-row frag
    const int a_c = lane >> 4;              // A: 8-col block (0/1)
    const int b_r = lane & 7;               // B: row within 8-row group
    const int b_c = (lane >> 3) & 1;        // B: k-chunk select
    const int b_g = (lane >> 4) & 1;        // B: which of the ni pair

    for (int kt = 0; kt < NKT; kt++) {
        cp_wait<GSTAGES - 2>();
        __syncthreads();                    // all warps done with iter kt-1

        if (kt + GSTAGES - 1 < NKT)         // refill stage consumed last iter
            load_stage(kt + GSTAGES - 1, (kt + GSTAGES - 1) & (GSTAGES - 1));
        CP_COMMIT();

        const uint32_t sa = sbase + (kt & (GSTAGES - 1)) * STG_BYTES;
        const uint32_t sb = sa + A_STG;

        #pragma unroll
        for (int ks = 0; ks < 2; ks++) {
            uint32_t afr[4][4], bfr[4][2];
            #pragma unroll
            for (int mi = 0; mi < 4; mi++) {
                int row = wm * 64 + mi * 16 + a_r;
                int c   = ks * 2 + a_c;
                ldsm_x4(afr[mi], sa + row * 64 + ((c ^ ((row >> 1) & 3)) * 16));
            }
            #pragma unroll
            for (int np = 0; np < 2; np++) {   // ni pairs (0,1) and (2,3)
                int row = wn * 32 + (np * 2 + b_g) * 8 + b_r;
                int c   = ks * 2 + b_c;
                ldsm_x4(&bfr[np * 2][0],
                        sb + row * 64 + ((c ^ ((row >> 1) & 3)) * 16));
            }
            #pragma unroll
            for (int mi = 0; mi < 4; mi++)
                #pragma unroll
                for (int ni = 0; ni < 4; ni++)
                    mma_f16(acc[mi][ni], afr[mi], bfr[ni]);
        }
        // no trailing sync: top-of-loop sync covers stage-reuse hazard
    }

    const int er = lane >> 2;
    const int ec = (lane & 3) * 2;
    #pragma unroll
    for (int mi = 0; mi < 4; mi++) {
        #pragma unroll
        for (int ni = 0; ni < 4; ni++) {
            int gr = m0 + wm * 64 + mi * 16 + er;
            int gc = n0 + wn * 32 + ni * 8 + ec;
            float2 v0 = make_float2(acc[mi][ni][0], acc[mi][ni][1]);
            float2 v1 = make_float2(acc[mi][ni][2], acc[mi][ni][3]);
            *(float2*)&C[(size_t)gr * HH + gc]       = v0;
            *(float2*)&C[(size_t)(gr + 8) * HH + gc] = v1;
        }
    }
}

// ---------------------------------------------------------------------------
// Scan: 1 thread per (b, h). cp.async ring (depth 15) hides DRAM latency;
// MUFU-based activations (~2 ulp) cut issue count ~2.5x vs libm.
// ---------------------------------------------------------------------------
#define STAGES 16

__global__ __launch_bounds__(128)
void brc_scan_kernel(const float* __restrict__ h0,
                     const float* __restrict__ mz,
                     const float* __restrict__ mr,
                     const float* __restrict__ bz,
                     const float* __restrict__ br,
                     float* __restrict__ out)
{
    __shared__ float ring[STAGES][3][128];

    const int tid = threadIdx.x;
    const int idx = blockIdx.x * 128 + tid;
    const int b = idx >> 9;
    const int h = idx & 511;

    float hc        = h0[idx];
    const float vmz = mz[h];
    const float vmr = mr[h];
    const float vbz = bz[h];
    const float vbr = br[h];

    const float* __restrict__ xz = g_proj[0];
    const float* __restrict__ xr = g_proj[1];
    const float* __restrict__ xh = g_proj[2];

    const size_t base = (size_t)b * TT * HH + h;

    const uint32_t s0 = smem_u32(&ring[0][0][tid]);
    const uint32_t stage_stride = 3 * 128 * 4;
    const uint32_t arr_stride   = 128 * 4;

    #pragma unroll
    for (int s = 0; s < STAGES - 1; s++) {          // prologue: stages 0..14
        size_t off = base + (size_t)s * HH;
        uint32_t sa = s0 + s * stage_stride;
        cpa4(sa,                  xz + off);
        cpa4(sa + arr_stride,     xr + off);
        cpa4(sa + 2 * arr_stride, xh + off);
        CP_COMMIT();
    }

    for (int t = 0; t < TT; t++) {
        cp_wait<STAGES - 2>();                      // stage t landed
        const int s = t & (STAGES - 1);
        float az = ring[s][0][tid] + vbz;
        float ar = ring[s][1][tid] + vbr;
        float ah = ring[s][2][tid];

        float r    = tanh_fast2(fmaf(hc, vmr, ar)) + 1.0f;
        float zg   = sigmoid_fast(fmaf(hc, vmz, az));
        float cand = tanh_fast2(fmaf(r, hc, ah));
        hc = fmaf(zg, hc - cand, cand);

        out[base + (size_t)t * HH] = hc;

        const int tn = t + STAGES - 1;              // refill consumed stage
        if (tn < TT) {
            size_t off = base + (size_t)tn * HH;
            uint32_t sa = s0 + (tn & (STAGES - 1)) * stage_stride;
            cpa4(sa,                  xz + off);
            cpa4(sa + arr_stride,     xr + off);
            cpa4(sa + 2 * arr_stride, xh + off);
        }
        CP_COMMIT();                                // keep group count stable
    }
}

// ---------------------------------------------------------------------------
// Launch. Inputs: x, h0, kz, kr, kh, mz, mr, bz, br. Output: [B, T, H] fp32.
// ---------------------------------------------------------------------------
extern "C" void kernel_launch(void* const* d_in, const int* in_sizes, int n_in,
                              void* d_out, int out_size)
{
    const float* x  = (const float*)d_in[0];
    const float* h0 = (const float*)d_in[1];
    const float* kz = (const float*)d_in[2];
    const float* kr = (const float*)d_in[3];
    const float* kh = (const float*)d_in[4];
    const float* mz = (const float*)d_in[5];
    const float* mr = (const float*)d_in[6];
    const float* bz = (const float*)d_in[7];
    const float* br = (const float*)d_in[8];
    float* out = (float*)d_out;

    cudaFuncSetAttribute(brc_mma_gemm, cudaFuncAttributeMaxDynamicSharedMemorySize,
                         GSMEM);

    cvt_x_kernel<<<(MM * KK / 4) / 256, 256>>>(x);
    cvt_w_kernel<<<dim3(16, 16, 3), dim3(32, 8)>>>(kz, kr, kh);

    dim3 ggrid(12, MM / GBM);          // (w, n-tile) fast -> A m-block L2 reuse x12
    brc_mma_gemm<<<ggrid, 256, GSMEM>>>();

    brc_scan_kernel<<<(BB * HH) / 128, 128>>>(h0, mz, mr, bz, br, out);
}

// round 6
// speedup vs baseline: 5.8985x; 1.5047x over previous
#include <cuda_runtime.h>
#include <cuda_fp16.h>
#include <cstdint>
#include <math.h>

// Problem constants: B=64, T=512, K=512, H=512. M = B*T = 32768.
#define BB   64
#define TT   512
#define KK   512
#define HH   512
#define MM   (BB * TT)          // 32768

// ---------------------------------------------------------------------------
// Scratch (__device__ globals; no allocations allowed)
// ---------------------------------------------------------------------------
__device__ __half g_projh[3][(size_t)MM * HH];       // xz, xr, xh (fp16)
__device__ __half g_xs[(size_t)MM * KK];             // x in fp16
__device__ __half g_ws[3ull * HH * KK];              // W^T in fp16: [w][n][k]

// ---------------------------------------------------------------------------
// Helpers (sm_80-compatible PTX: ldmatrix / mma.sync / cp.async)
// ---------------------------------------------------------------------------
__device__ __forceinline__ uint32_t smem_u32(const void* p) {
    uint32_t a;
    asm("{ .reg .u64 t; cvta.to.shared.u64 t, %1; cvt.u32.u64 %0, t; }" : "=r"(a) : "l"(p));
    return a;
}

__device__ __forceinline__ void cpa16(uint32_t saddr, const void* g) {
    asm volatile("cp.async.cg.shared.global [%0], [%1], 16;" :: "r"(saddr), "l"(g));
}
__device__ __forceinline__ void cpa4(uint32_t saddr, const void* g) {
    asm volatile("cp.async.ca.shared.global [%0], [%1], 4;" :: "r"(saddr), "l"(g));
}
#define CP_COMMIT() asm volatile("cp.async.commit_group;" ::: "memory")
template <int N>
__device__ __forceinline__ void cp_wait() {
    asm volatile("cp.async.wait_group %0;" :: "n"(N) : "memory");
}

__device__ __forceinline__ void ldsm_x4(uint32_t* r, uint32_t addr) {
    asm volatile("ldmatrix.sync.aligned.m8n8.x4.shared.b16 {%0,%1,%2,%3}, [%4];"
                 : "=r"(r[0]), "=r"(r[1]), "=r"(r[2]), "=r"(r[3]) : "r"(addr));
}
__device__ __forceinline__ void mma_f16(float* d, const uint32_t* a, const uint32_t* b) {
    asm volatile(
        "mma.sync.aligned.m16n8k16.row.col.f32.f16.f16.f32 "
        "{%0,%1,%2,%3}, {%4,%5,%6,%7}, {%8,%9}, {%0,%1,%2,%3};"
        : "+f"(d[0]), "+f"(d[1]), "+f"(d[2]), "+f"(d[3])
        : "r"(a[0]), "r"(a[1]), "r"(a[2]), "r"(a[3]), "r"(b[0]), "r"(b[1]));
}

// Fast activations: MUFU-based, ~2 ulp, robust at +/-inf.
__device__ __forceinline__ float sigmoid_fast(float x) {
    return __fdividef(1.0f, 1.0f + __expf(-x));
}
__device__ __forceinline__ float tanh_fast2(float x) {
    return __fdividef(2.0f, 1.0f + __expf(-2.0f * x)) - 1.0f;
}

// ---------------------------------------------------------------------------
// Convert x: linear fp32 -> fp16. 8 elements / thread.
// ---------------------------------------------------------------------------
__global__ void cvt_x_kernel(const float* __restrict__ x) {
    size_t i = ((size_t)blockIdx.x * blockDim.x + threadIdx.x) * 8;
    float4 v0 = *(const float4*)(x + i);
    float4 v1 = *(const float4*)(x + i + 4);
    __half2 h[4];
    h[0] = __floats2half2_rn(v0.x, v0.y);
    h[1] = __floats2half2_rn(v0.z, v0.w);
    h[2] = __floats2half2_rn(v1.x, v1.y);
    h[3] = __floats2half2_rn(v1.z, v1.w);
    *(uint4*)(g_xs + i) = *(uint4*)h;
}

// ---------------------------------------------------------------------------
// Convert weights with coalesced smem transpose: W[k][n] -> W^T[w][n][k] fp16.
// ---------------------------------------------------------------------------
__global__ void cvt_w_kernel(const float* __restrict__ kz,
                             const float* __restrict__ kr,
                             const float* __restrict__ kh) {
    __shared__ float tile[32][33];
    const int w  = blockIdx.z;
    const int k0 = blockIdx.x * 32;
    const int n0 = blockIdx.y * 32;
    const int tx = threadIdx.x, ty = threadIdx.y;
    const float* __restrict__ W = (w == 0) ? kz : (w == 1) ? kr : kh;

    #pragma unroll
    for (int r = 0; r < 4; r++)
        tile[ty + r * 8][tx] = W[(size_t)(k0 + ty + r * 8) * HH + n0 + tx];
    __syncthreads();

    #pragma unroll
    for (int r = 0; r < 4; r++) {
        int n = n0 + ty + r * 8;
        int k = k0 + tx;
        g_ws[((size_t)w * HH + n) * KK + k] = __float2half_rn(tile[tx][ty + r * 8]);
    }
}

// ---------------------------------------------------------------------------
// GEMM: g_projh[w] = fp16(A(32768 x 512) @ W_w), fp16 mma.sync, fp32 accum.
// Block 128x128x32, 8 warps (2m x 4n -> 64x32 warp tiles), 4-stage cp.async.
// Smem rows 64B (4 x 16B chunks), XOR swizzle chunk ^= (row>>1)&3.
// ---------------------------------------------------------------------------
#define GBM 128
#define GBN 128
#define GBK 32
#define NKT (KK / GBK)          // 16
#define GSTAGES 4
#define A_STG (GBM * GBK * 2)   // 8192 B
#define B_STG (GBN * GBK * 2)   // 8192 B
#define STG_BYTES (A_STG + B_STG)
#define GSMEM (GSTAGES * STG_BYTES)   // 65536 B

__global__ __launch_bounds__(256, 2)
void brc_mma_gemm(void) {
    extern __shared__ char smem[];
    const uint32_t sbase = smem_u32(smem);
    const int tid  = threadIdx.x;
    const int lane = tid & 31;
    const int wid  = tid >> 5;
    const int wm   = wid >> 2;          // 0..1  (m group)
    const int wn   = wid & 3;           // 0..3  (n group)

    const int w  = blockIdx.x >> 2;
    const int n0 = (blockIdx.x & 3) * GBN;
    const int m0 = blockIdx.y * GBM;

    const __half* __restrict__ Ap = g_xs;
    const __half* __restrict__ Bp = g_ws + (size_t)w * HH * KK;
    __half* __restrict__ C = g_projh[w];

    // per-thread load slots: chunks tid and tid+256 of 512 (row = c>>2, chunk = c&3)
    const int lrow0 = tid >> 2,          lc0 = tid & 3;
    const int lrow1 = (tid + 256) >> 2,  lc1 = (tid + 256) & 3;
    const uint32_t so0 = lrow0 * 64 + ((lc0 ^ ((lrow0 >> 1) & 3)) * 16);
    const uint32_t so1 = lrow1 * 64 + ((lc1 ^ ((lrow1 >> 1) & 3)) * 16);

    auto load_stage = [&](int kt, int s) {
        const uint32_t sa = sbase + s * STG_BYTES;
        const uint32_t sb = sa + A_STG;
        const size_t kb = (size_t)kt * GBK;
        cpa16(sa + so0, Ap + (size_t)(m0 + lrow0) * KK + kb + lc0 * 8);
        cpa16(sa + so1, Ap + (size_t)(m0 + lrow1) * KK + kb + lc1 * 8);
        cpa16(sb + so0, Bp + (size_t)(n0 + lrow0) * KK + kb + lc0 * 8);
        cpa16(sb + so1, Bp + (size_t)(n0 + lrow1) * KK + kb + lc1 * 8);
    };

    #pragma unroll
    for (int s = 0; s < GSTAGES - 1; s++) { load_stage(s, s); CP_COMMIT(); }

    float acc[4][4][4];
    #pragma unroll
    for (int i = 0; i < 4; i++)
        #pragma unroll
        for (int j = 0; j < 4; j++)
            #pragma unroll
            for (int q = 0; q < 4; q++) acc[i][j][q] = 0.0f;

    // ldmatrix lane geometry
    const int a_r = lane & 15;              // A: row within 16-row frag
    const int a_c = lane >> 4;              // A: 8-col block (0/1)
    const int b_r = lane & 7;               // B: row within 8-row group
    const int b_c = (lane >> 3) & 1;        // B: k-chunk select
    const int b_g = (lane >> 4) & 1;        // B: which of the ni pair

    for (int kt = 0; kt < NKT; kt++) {
        cp_wait<GSTAGES - 2>();
        __syncthreads();                    // all warps done with iter kt-1

        if (kt + GSTAGES - 1 < NKT)         // refill stage consumed last iter
            load_stage(kt + GSTAGES - 1, (kt + GSTAGES - 1) & (GSTAGES - 1));
        CP_COMMIT();

        const uint32_t sa = sbase + (kt & (GSTAGES - 1)) * STG_BYTES;
        const uint32_t sb = sa + A_STG;

        #pragma unroll
        for (int ks = 0; ks < 2; ks++) {
            uint32_t afr[4][4], bfr[4][2];
            #pragma unroll
            for (int mi = 0; mi < 4; mi++) {
                int row = wm * 64 + mi * 16 + a_r;
                int c   = ks * 2 + a_c;
                ldsm_x4(afr[mi], sa + row * 64 + ((c ^ ((row >> 1) & 3)) * 16));
            }
            #pragma unroll
            for (int np = 0; np < 2; np++) {   // ni pairs (0,1) and (2,3)
                int row = wn * 32 + (np * 2 + b_g) * 8 + b_r;
                int c   = ks * 2 + b_c;
                ldsm_x4(&bfr[np * 2][0],
                        sb + row * 64 + ((c ^ ((row >> 1) & 3)) * 16));
            }
            #pragma unroll
            for (int mi = 0; mi < 4; mi++)
                #pragma unroll
                for (int ni = 0; ni < 4; ni++)
                    mma_f16(acc[mi][ni], afr[mi], bfr[ni]);
        }
        // no trailing sync: top-of-loop sync covers stage-reuse hazard
    }

    // epilogue: fp16 store. thread holds cols (ec, ec+1) -> one half2 each row.
    const int er = lane >> 2;
    const int ec = (lane & 3) * 2;
    #pragma unroll
    for (int mi = 0; mi < 4; mi++) {
        #pragma unroll
        for (int ni = 0; ni < 4; ni++) {
            int gr = m0 + wm * 64 + mi * 16 + er;
            int gc = n0 + wn * 32 + ni * 8 + ec;
            __half2 v0 = __floats2half2_rn(acc[mi][ni][0], acc[mi][ni][1]);
            __half2 v1 = __floats2half2_rn(acc[mi][ni][2], acc[mi][ni][3]);
            *(__half2*)&C[(size_t)gr * HH + gc]       = v0;
            *(__half2*)&C[(size_t)(gr + 8) * HH + gc] = v1;
        }
    }
}

// ---------------------------------------------------------------------------
// Scan: ILP-2 — each thread owns channels (h, h+1); two independent
// recurrence chains interleave to hide the serial-dependency latency.
// fp16 pair loads = 4B cp.async; depth-15 ring.
// Blocks of 64 threads x 256 blocks keep all 148 SMs occupied.
// ---------------------------------------------------------------------------
#define STAGES 16
#define SCAN_T 64

__global__ __launch_bounds__(SCAN_T)
void brc_scan_kernel(const float* __restrict__ h0,
                     const float* __restrict__ mz,
                     const float* __restrict__ mr,
                     const float* __restrict__ bz,
                     const float* __restrict__ br,
                     float* __restrict__ out)
{
    __shared__ uint32_t ring[STAGES][3][SCAN_T];

    const int tid  = threadIdx.x;
    const int idx2 = blockIdx.x * SCAN_T + tid;     // pair index 0..16383
    const int b    = idx2 >> 8;                     // 256 pairs per batch
    const int h    = (idx2 & 255) * 2;

    float2 hc  = *(const float2*)&h0[b * HH + h];
    const float2 vmz = *(const float2*)&mz[h];
    const float2 vmr = *(const float2*)&mr[h];
    const float2 vbz = *(const float2*)&bz[h];
    const float2 vbr = *(const float2*)&br[h];

    const __half* __restrict__ xz = g_projh[0];
    const __half* __restrict__ xr = g_projh[1];
    const __half* __restrict__ xh = g_projh[2];

    const size_t base = (size_t)b * TT * HH + h;

    const uint32_t s0 = smem_u32(&ring[0][0][tid]);
    const uint32_t stage_stride = 3 * SCAN_T * 4;
    const uint32_t arr_stride   = SCAN_T * 4;

    #pragma unroll
    for (int s = 0; s < STAGES - 1; s++) {          // prologue: stages 0..14
        size_t off = base + (size_t)s * HH;
        uint32_t sa = s0 + s * stage_stride;
        cpa4(sa,                  xz + off);
        cpa4(sa + arr_stride,     xr + off);
        cpa4(sa + 2 * arr_stride, xh + off);
        CP_COMMIT();
    }

    for (int t = 0; t < TT; t++) {
        cp_wait<STAGES - 2>();                      // stage t landed
        const int s = t & (STAGES - 1);
        uint32_t uz = ring[s][0][tid];
        uint32_t ur = ring[s][1][tid];
        uint32_t uh = ring[s][2][tid];
        float2 pz = __half22float2(*(__half2*)&uz);
        float2 pr = __half22float2(*(__half2*)&ur);
        float2 ph = __half22float2(*(__half2*)&uh);

        // channel 0
        float r0 = tanh_fast2(fmaf(hc.x, vmr.x, pr.x + vbr.x)) + 1.0f;
        float z0 = sigmoid_fast(fmaf(hc.x, vmz.x, pz.x + vbz.x));
        float c0 = tanh_fast2(fmaf(r0, hc.x, ph.x));
        // channel 1 (independent chain)
        float r1 = tanh_fast2(fmaf(hc.y, vmr.y, pr.y + vbr.y)) + 1.0f;
        float z1 = sigmoid_fast(fmaf(hc.y, vmz.y, pz.y + vbz.y));
        float c1 = tanh_fast2(fmaf(r1, hc.y, ph.y));

        hc.x = fmaf(z0, hc.x - c0, c0);
        hc.y = fmaf(z1, hc.y - c1, c1);

        *(float2*)&out[base + (size_t)t * HH] = hc;

        const int tn = t + STAGES - 1;              // refill consumed stage
        if (tn < TT) {
            size_t off = base + (size_t)tn * HH;
            uint32_t sa = s0 + (tn & (STAGES - 1)) * stage_stride;
            cpa4(sa,                  xz + off);
            cpa4(sa + arr_stride,     xr + off);
            cpa4(sa + 2 * arr_stride, xh + off);
        }
        CP_COMMIT();                                // keep group count stable
    }
}

// ---------------------------------------------------------------------------
// Launch. Inputs: x, h0, kz, kr, kh, mz, mr, bz, br. Output: [B, T, H] fp32.
// ---------------------------------------------------------------------------
extern "C" void kernel_launch(void* const* d_in, const int* in_sizes, int n_in,
                              void* d_out, int out_size)
{
    const float* x  = (const float*)d_in[0];
    const float* h0 = (const float*)d_in[1];
    const float* kz = (const float*)d_in[2];
    const float* kr = (const float*)d_in[3];
    const float* kh = (const float*)d_in[4];
    const float* mz = (const float*)d_in[5];
    const float* mr = (const float*)d_in[6];
    const float* bz = (const float*)d_in[7];
    const float* br = (const float*)d_in[8];
    float* out = (float*)d_out;

    cudaFuncSetAttribute(brc_mma_gemm, cudaFuncAttributeMaxDynamicSharedMemorySize,
                         GSMEM);

    cvt_x_kernel<<<(MM * KK / 8) / 256, 256>>>(x);
    cvt_w_kernel<<<dim3(16, 16, 3), dim3(32, 8)>>>(kz, kr, kh);

    dim3 ggrid(12, MM / GBM);          // (w, n-tile) fast -> A m-block L2 reuse x12
    brc_mma_gemm<<<ggrid, 256, GSMEM>>>();

    brc_scan_kernel<<<(BB * HH / 2) / SCAN_T, SCAN_T>>>(h0, mz, mr, bz, br, out);
}

// round 8
// speedup vs baseline: 6.9397x; 1.1765x over previous
#include <cuda_runtime.h>
#include <cuda_fp16.h>
#include <cstdint>
#include <math.h>

// Problem constants: B=64, T=512, K=512, H=512. M = B*T = 32768.
#define BB   64
#define TT   512
#define KK   512
#define HH   512
#define MM   (BB * TT)          // 32768

// ---------------------------------------------------------------------------
// Scratch (__device__ globals; no allocations allowed)
// ---------------------------------------------------------------------------
__device__ __half g_projh[3][(size_t)MM * HH];       // xz, xr, xh (fp16)
__device__ __half g_xs[(size_t)MM * KK];             // x in fp16
__device__ __half g_ws[3ull * HH * KK];              // W^T in fp16: [w][n][k]

// ---------------------------------------------------------------------------
// Helpers (sm_80-compatible PTX: ldmatrix / mma.sync / cp.async)
// ---------------------------------------------------------------------------
__device__ __forceinline__ uint32_t smem_u32(const void* p) {
    uint32_t a;
    asm("{ .reg .u64 t; cvta.to.shared.u64 t, %1; cvt.u32.u64 %0, t; }" : "=r"(a) : "l"(p));
    return a;
}

__device__ __forceinline__ void cpa16(uint32_t saddr, const void* g) {
    asm volatile("cp.async.cg.shared.global [%0], [%1], 16;" :: "r"(saddr), "l"(g));
}
__device__ __forceinline__ void cpa4(uint32_t saddr, const void* g) {
    asm volatile("cp.async.ca.shared.global [%0], [%1], 4;" :: "r"(saddr), "l"(g));
}
#define CP_COMMIT() asm volatile("cp.async.commit_group;" ::: "memory")
template <int N>
__device__ __forceinline__ void cp_wait() {
    asm volatile("cp.async.wait_group %0;" :: "n"(N) : "memory");
}

__device__ __forceinline__ void ldsm_x4(uint32_t* r, uint32_t addr) {
    asm volatile("ldmatrix.sync.aligned.m8n8.x4.shared.b16 {%0,%1,%2,%3}, [%4];"
                 : "=r"(r[0]), "=r"(r[1]), "=r"(r[2]), "=r"(r[3]) : "r"(addr));
}
__device__ __forceinline__ void mma_f16(float* d, const uint32_t* a, const uint32_t* b) {
    asm volatile(
        "mma.sync.aligned.m16n8k16.row.col.f32.f16.f16.f32 "
        "{%0,%1,%2,%3}, {%4,%5,%6,%7}, {%8,%9}, {%0,%1,%2,%3};"
        : "+f"(d[0]), "+f"(d[1]), "+f"(d[2]), "+f"(d[3])
        : "r"(a[0]), "r"(a[1]), "r"(a[2]), "r"(a[3]), "r"(b[0]), "r"(b[1]));
}

// Single-MUFU tanh; sigmoid via exact identity s(x) = 0.5*tanh(x/2) + 0.5.
__device__ __forceinline__ float tanh_approx(float x) {
    float y;
    asm("tanh.approx.f32 %0, %1;" : "=f"(y) : "f"(x));
    return y;
}

// ---------------------------------------------------------------------------
// Convert x: linear fp32 -> fp16. 8 elements / thread.
// ---------------------------------------------------------------------------
__global__ void cvt_x_kernel(const float* __restrict__ x) {
    size_t i = ((size_t)blockIdx.x * blockDim.x + threadIdx.x) * 8;
    float4 v0 = *(const float4*)(x + i);
    float4 v1 = *(const float4*)(x + i + 4);
    __half2 h[4];
    h[0] = __floats2half2_rn(v0.x, v0.y);
    h[1] = __floats2half2_rn(v0.z, v0.w);
    h[2] = __floats2half2_rn(v1.x, v1.y);
    h[3] = __floats2half2_rn(v1.z, v1.w);
    *(uint4*)(g_xs + i) = *(uint4*)h;
}

// ---------------------------------------------------------------------------
// Convert weights with coalesced smem transpose: W[k][n] -> W^T[w][n][k] fp16.
// ---------------------------------------------------------------------------
__global__ void cvt_w_kernel(const float* __restrict__ kz,
                             const float* __restrict__ kr,
                             const float* __restrict__ kh) {
    __shared__ float tile[32][33];
    const int w  = blockIdx.z;
    const int k0 = blockIdx.x * 32;
    const int n0 = blockIdx.y * 32;
    const int tx = threadIdx.x, ty = threadIdx.y;
    const float* __restrict__ W = (w == 0) ? kz : (w == 1) ? kr : kh;

    #pragma unroll
    for (int r = 0; r < 4; r++)
        tile[ty + r * 8][tx] = W[(size_t)(k0 + ty + r * 8) * HH + n0 + tx];
    __syncthreads();

    #pragma unroll
    for (int r = 0; r < 4; r++) {
        int n = n0 + ty + r * 8;
        int k = k0 + tx;
        g_ws[((size_t)w * HH + n) * KK + k] = __float2half_rn(tile[tx][ty + r * 8]);
    }
}

// ---------------------------------------------------------------------------
// GEMM: g_projh[w] = fp16(A(32768 x 512) @ W_w), fp16 mma.sync, fp32 accum.
// Block 128x128x64, 8 warps (2m x 4n -> 64x32 warp tiles), 3-stage cp.async.
// Smem rows 128B (8 x 16B chunks), swizzle chunk ^= row&7 -> conflict-free
// ldmatrix (the old (row>>1)&3 swizzle had 2-way conflicts on every LDSM).
// ---------------------------------------------------------------------------
#define GBM 128
#define GBN 128
#define GBK 64
#define NKT (KK / GBK)          // 8
#define GSTAGES 3
#define A_STG (GBM * GBK * 2)   // 16384 B
#define B_STG (GBN * GBK * 2)   // 16384 B
#define STG_BYTES (A_STG + B_STG)
#define GSMEM (GSTAGES * STG_BYTES)   // 98304 B

__global__ __launch_bounds__(256, 2)
void brc_mma_gemm(void) {
    extern __shared__ char smem[];
    const uint32_t sbase = smem_u32(smem);
    const int tid  = threadIdx.x;
    const int lane = tid & 31;
    const int wid  = tid >> 5;
    const int wm   = wid >> 2;          // 0..1  (m group)
    const int wn   = wid & 3;           // 0..3  (n group)

    const int w  = blockIdx.x >> 2;
    const int n0 = (blockIdx.x & 3) * GBN;
    const int m0 = blockIdx.y * GBM;

    const __half* __restrict__ Ap = g_xs;
    const __half* __restrict__ Bp = g_ws + (size_t)w * HH * KK;
    __half* __restrict__ C = g_projh[w];

    // loads: 1024 16B-chunks per operand per stage; 4 per thread per operand.
    // chunk j: row = j>>3 (0..127), c = j&7; phys chunk = c ^ (row&7).
    auto load_stage = [&](int kt, int s) {
        const uint32_t sa = sbase + s * STG_BYTES;
        const uint32_t sb = sa + A_STG;
        const size_t kb = (size_t)kt * GBK;
        #pragma unroll
        for (int q = 0; q < 4; q++) {
            int j   = tid + q * 256;
            int row = j >> 3, c = j & 7;
            uint32_t so = row * 128 + ((c ^ (row & 7)) * 16);
            cpa16(sa + so, Ap + (size_t)(m0 + row) * KK + kb + c * 8);
            cpa16(sb + so, Bp + (size_t)(n0 + row) * KK + kb + c * 8);
        }
    };

    load_stage(0, 0); CP_COMMIT();
    load_stage(1, 1); CP_COMMIT();

    float acc[4][4][4];
    #pragma unroll
    for (int i = 0; i < 4; i++)
        #pragma unroll
        for (int j = 0; j < 4; j++)
            #pragma unroll
            for (int q = 0; q < 4; q++) acc[i][j][q] = 0.0f;

    // ldmatrix lane geometry
    const int a_r = lane & 15;              // A: row within 16-row frag
    const int a_c = lane >> 4;              // A: k-chunk select (0/1)
    const int b_r = lane & 7;               // B: row within 8-row group
    const int b_c = (lane >> 3) & 1;        // B: k-chunk select
    const int b_g = (lane >> 4) & 1;        // B: which of the ni pair

    int sl = 0;                             // slot of stage kt (mod 3 counter)
    for (int kt = 0; kt < NKT; kt++) {
        cp_wait<GSTAGES - 2>();
        __syncthreads();                    // all warps done reading slot of kt-1

        if (kt + 2 < NKT) {
            int ps = sl + 2; if (ps >= 3) ps -= 3;   // == slot of stage kt-1
            load_stage(kt + 2, ps);
        }
        CP_COMMIT();

        const uint32_t sa = sbase + sl * STG_BYTES;
        const uint32_t sb = sa + A_STG;

        #pragma unroll
        for (int ks = 0; ks < 4; ks++) {
            uint32_t afr[4][4], bfr[4][2];
            #pragma unroll
            for (int mi = 0; mi < 4; mi++) {
                int row = wm * 64 + mi * 16 + a_r;
                int c   = ks * 2 + a_c;
                ldsm_x4(afr[mi], sa + row * 128 + ((c ^ (row & 7)) * 16));
            }
            #pragma unroll
            for (int np = 0; np < 2; np++) {   // ni pairs (0,1) and (2,3)
                int row = wn * 32 + (np * 2 + b_g) * 8 + b_r;
                int c   = ks * 2 + b_c;
                ldsm_x4(&bfr[np * 2][0],
                        sb + row * 128 + ((c ^ (row & 7)) * 16));
            }
            #pragma unroll
            for (int mi = 0; mi < 4; mi++)
                #pragma unroll
                for (int ni = 0; ni < 4; ni++)
                    mma_f16(acc[mi][ni], afr[mi], bfr[ni]);
        }
        if (++sl == 3) sl = 0;
        // no trailing sync: top-of-loop sync covers slot-reuse hazard
    }

    // epilogue: fp16 store; thread holds cols (ec, ec+1) -> one half2 per row.
    const int er = lane >> 2;
    const int ec = (lane & 3) * 2;
    #pragma unroll
    for (int mi = 0; mi < 4; mi++) {
        #pragma unroll
        for (int ni = 0; ni < 4; ni++) {
            int gr = m0 + wm * 64 + mi * 16 + er;
            int gc = n0 + wn * 32 + ni * 8 + ec;
            __half2 v0 = __floats2half2_rn(acc[mi][ni][0], acc[mi][ni][1]);
            __half2 v1 = __floats2half2_rn(acc[mi][ni][2], acc[mi][ni][3]);
            *(__half2*)&C[(size_t)gr * HH + gc]       = v0;
            *(__half2*)&C[(size_t)(gr + 8) * HH + gc] = v1;
        }
    }
}

// ---------------------------------------------------------------------------
// Scan: ILP-2 (thread owns channels h, h+1), SINGLE WAVE: 128 blocks x 128
// threads on 148 SMs (256 blocks paid 1.73 waves of a latency-bound kernel).
// tanh.approx (1 MUFU) for all activations; sigmoid = 0.5*tanh(x/2) + 0.5.
// ---------------------------------------------------------------------------
#define STAGES 16
#define SCAN_T 128

__global__ __launch_bounds__(SCAN_T)
void brc_scan_kernel(const float* __restrict__ h0,
                     const float* __restrict__ mz,
                     const float* __restrict__ mr,
                     const float* __restrict__ bz,
                     const float* __restrict__ br,
                     float* __restrict__ out)
{
    __shared__ uint32_t ring[STAGES][3][SCAN_T];

    const int tid  = threadIdx.x;
    const int idx2 = blockIdx.x * SCAN_T + tid;     // pair index 0..16383
    const int b    = idx2 >> 8;                     // 256 pairs per batch
    const int h    = (idx2 & 255) * 2;

    float2 hc  = *(const float2*)&h0[b * HH + h];
    const float2 vmz = *(const float2*)&mz[h];
    const float2 vmr = *(const float2*)&mr[h];
    const float2 vbz = *(const float2*)&bz[h];
    const float2 vbr = *(const float2*)&br[h];

    const __half* __restrict__ xz = g_projh[0];
    const __half* __restrict__ xr = g_projh[1];
    const __half* __restrict__ xh = g_projh[2];

    const size_t base = (size_t)b * TT * HH + h;

    const uint32_t s0 = smem_u32(&ring[0][0][tid]);
    const uint32_t stage_stride = 3 * SCAN_T * 4;
    const uint32_t arr_stride   = SCAN_T * 4;

    #pragma unroll
    for (int s = 0; s < STAGES - 1; s++) {          // prologue: stages 0..14
        size_t off = base + (size_t)s * HH;
        uint32_t sa = s0 + s * stage_stride;
        cpa4(sa,                  xz + off);
        cpa4(sa + arr_stride,     xr + off);
        cpa4(sa + 2 * arr_stride, xh + off);
        CP_COMMIT();
    }

    for (int t = 0; t < TT; t++) {
        cp_wait<STAGES - 2>();                      // stage t landed
        const int s = t & (STAGES - 1);
        uint32_t uz = ring[s][0][tid];
        uint32_t ur = ring[s][1][tid];
        uint32_t uh = ring[s][2][tid];
        float2 pz = __half22float2(*(__half2*)&uz);
        float2 pr = __half22float2(*(__half2*)&ur);
        float2 ph = __half22float2(*(__half2*)&uh);

        // channel 0
        float r0 = tanh_approx(fmaf(hc.x, vmr.x, pr.x + vbr.x)) + 1.0f;
        float z0 = fmaf(0.5f, tanh_approx(0.5f * fmaf(hc.x, vmz.x, pz.x + vbz.x)), 0.5f);
        float c0 = tanh_approx(fmaf(r0, hc.x, ph.x));
        // channel 1 (independent chain)
        float r1 = tanh_approx(fmaf(hc.y, vmr.y, pr.y + vbr.y)) + 1.0f;
        float z1 = fmaf(0.5f, tanh_approx(0.5f * fmaf(hc.y, vmz.y, pz.y + vbz.y)), 0.5f);
        float c1 = tanh_approx(fmaf(r1, hc.y, ph.y));

        hc.x = fmaf(z0, hc.x - c0, c0);
        hc.y = fmaf(z1, hc.y - c1, c1);

        *(float2*)&out[base + (size_t)t * HH] = hc;

        const int tn = t + STAGES - 1;              // refill consumed stage
        if (tn < TT) {
            size_t off = base + (size_t)tn * HH;
            uint32_t sa = s0 + (tn & (STAGES - 1)) * stage_stride;
            cpa4(sa,                  xz + off);
            cpa4(sa + arr_stride,     xr + off);
            cpa4(sa + 2 * arr_stride, xh + off);
        }
        CP_COMMIT();                                // keep group count stable
    }
}

// ---------------------------------------------------------------------------
// Launch. Inputs: x, h0, kz, kr, kh, mz, mr, bz, br. Output: [B, T, H] fp32.
// ---------------------------------------------------------------------------
extern "C" void kernel_launch(void* const* d_in, const int* in_sizes, int n_in,
                              void* d_out, int out_size)
{
    const float* x  = (const float*)d_in[0];
    const float* h0 = (const float*)d_in[1];
    const float* kz = (const float*)d_in[2];
    const float* kr = (const float*)d_in[3];
    const float* kh = (const float*)d_in[4];
    const float* mz = (const float*)d_in[5];
    const float* mr = (const float*)d_in[6];
    const float* bz = (const float*)d_in[7];
    const float* br = (const float*)d_in[8];
    float* out = (float*)d_out;

    cudaFuncSetAttribute(brc_mma_gemm, cudaFuncAttributeMaxDynamicSharedMemorySize,
                         GSMEM);

    cvt_x_kernel<<<(MM * KK / 8) / 256, 256>>>(x);
    cvt_w_kernel<<<dim3(16, 16, 3), dim3(32, 8)>>>(kz, kr, kh);

    dim3 ggrid(12, MM / GBM);          // (w, n-tile) fast -> A m-block L2 reuse x12
    brc_mma_gemm<<<ggrid, 256, GSMEM>>>();

    brc_scan_kernel<<<(BB * HH / 2) / SCAN_T, SCAN_T>>>(h0, mz, mr, bz, br, out);
}